// round 2
// baseline (speedup 1.0000x reference)
#include <cuda_runtime.h>
#include <math.h>

#define RANK 16
#define NF 32

typedef unsigned long long ull;

// ---- shared memory layout (float offsets) ----
#define OFF_W1P 0              // 32i x 4sp x 64 (lane-pair-major) = 8192
#define OFF_W2P 8192           // same layout                       = 8192
#define OFF_W3T 16384          // 256k x 33 (k-major, padded)       = 8448
#define OFF_Y0  24832          // 32 ch x 516 (512 + pad4)          = 16512
#define OFF_Y1  41344          // 8 q2 x 32 ch x 8 sub              = 2048
#define OFF_Y2  43392          // 32 ch x 8                         = 256
#define OFF_RED 43648          // 8 warps x 32                      = 256
#define OFF_W0D 43904          // 32 f x 8 s x 2 (duplicated)       = 512
#define OFF_B0D 44416          // 32 x 2 (duplicated)               = 64
#define OFF_B1  44480
#define OFF_B2  44512
#define OFF_B3  44544
#define OFF_FCW 44576
#define OFF_A   44608
#define OFF_B   44624
#define OFF_C   44640
#define SMEM_FLOATS 44656      // ~178.6 KB -> 1 CTA/SM

__device__ __forceinline__ ull pk2(float lo, float hi) {
    ull r; asm("mov.b64 %0,{%1,%2};" : "=l"(r) : "f"(lo), "f"(hi)); return r;
}
__device__ __forceinline__ void upk2(ull v, float& lo, float& hi) {
    asm("mov.b64 {%0,%1},%2;" : "=f"(lo), "=f"(hi) : "l"(v));
}
__device__ __forceinline__ ull fma2(ull a, ull b, ull c) {
    ull d; asm("fma.rn.f32x2 %0,%1,%2,%3;" : "=l"(d) : "l"(a), "l"(b), "l"(c)); return d;
}
__device__ __forceinline__ ull add2(ull a, ull b) {
    ull d; asm("add.rn.f32x2 %0,%1,%2;" : "=l"(d) : "l"(a), "l"(b)); return d;
}

extern "C" __global__ void __launch_bounds__(256, 1)
ntc_fused_kernel(const int* __restrict__ gi, const int* __restrict__ gj,
                 const int* __restrict__ gk,
                 const float* __restrict__ gA, const float* __restrict__ gB,
                 const float* __restrict__ gC,
                 const float* __restrict__ gW0, const float* __restrict__ gb0,
                 const float* __restrict__ gW1, const float* __restrict__ gb1,
                 const float* __restrict__ gW2, const float* __restrict__ gb2,
                 const float* __restrict__ gW3, const float* __restrict__ gb3,
                 const float* __restrict__ gfcw, const float* __restrict__ gfcb,
                 float* __restrict__ out, int batch, int gridSize)
{
    extern __shared__ float sm[];
    const int tid  = threadIdx.x;
    const int lane = tid & 31;
    const int wq   = tid >> 5;    // warp id 0..7

    // ---- one-time per-CTA weight staging ----
    for (int idx = tid; idx < NF * NF * 8; idx += 256) {
        int o = idx >> 8;          // out channel
        int k = idx & 255;         // i*8 + sub
        int pp = (k >> 1) * 64 + o * 2 + (k & 1);   // pair-major slot
        sm[OFF_W1P + pp] = gW1[idx];
        sm[OFF_W2P + pp] = gW2[idx];
        sm[OFF_W3T + k * 33 + o] = gW3[idx];
    }
    if (tid < 256) {               // W0 duplicated {w,w}
        float w = gW0[tid];
        sm[OFF_W0D + tid * 2]     = w;
        sm[OFF_W0D + tid * 2 + 1] = w;
    }
    if (tid < 64) sm[OFF_B0D + tid] = gb0[tid >> 1];
    if (tid < 32) {
        sm[OFF_B1 + tid]  = gb1[tid];
        sm[OFF_B2 + tid]  = gb2[tid];
        sm[OFF_B3 + tid]  = gb3[tid];
        sm[OFF_FCW + tid] = gfcw[tid];
    }
    const float fc_b = gfcb[0];
    __syncthreads();

    // conv0 per-thread geometry: tid = q0*8 + s0
    const int s0 = tid & 7;
    const int q0 = tid >> 3;

    // conv1 warp->position block map: warp wq owns the 8 conv1 positions whose
    // conv2 block index q2 == wq; sub-position s2 == p.
    int xoff[8];
    {
        int a = (wq >> 2) & 1, b = (wq >> 1) & 1, c = wq & 1;
        #pragma unroll
        for (int p = 0; p < 8; p++) {
            int q1 = (2 * a + (p >> 2)) * 16
                   + (2 * b + ((p >> 1) & 1)) * 4
                   + (2 * c + (p & 1));
            xoff[p] = q1 * 8;
        }
    }

    for (int sample = blockIdx.x; sample < batch; sample += gridSize) {
        // ---- gather a, b, c rows ----
        if (tid < 48) {
            int which = tid >> 4, t = tid & 15;
            if (which == 0)       sm[OFF_A + t] = gA[gi[sample] * RANK + t];
            else if (which == 1)  sm[OFF_B + t] = gB[gj[sample] * RANK + t];
            else                  sm[OFF_C + t] = gC[gk[sample] * RANK + t];
        }
        __syncthreads();

        // ---- conv0: rank-1 input; packed across the two half-positions ----
        ull abp[8];
        {
            float abc0[8], abc1[8];
            #pragma unroll
            for (int half = 0; half < 2; half++) {
                int q = q0 + half * 32;
                int d = 2 * (q >> 4)       + (s0 >> 2);
                int h = 2 * ((q >> 2) & 3) + ((s0 >> 1) & 1);
                int w = 2 * (q & 3)        + (s0 & 1);
                float a0 = sm[OFF_A + 2 * d], a1 = sm[OFF_A + 2 * d + 1];
                float b0 = sm[OFF_B + 2 * h], b1 = sm[OFF_B + 2 * h + 1];
                float c0 = sm[OFF_C + 2 * w], c1 = sm[OFF_C + 2 * w + 1];
                float* t = half ? abc1 : abc0;
                float a0b0 = a0 * b0, a0b1 = a0 * b1;
                float a1b0 = a1 * b0, a1b1 = a1 * b1;
                t[0] = a0b0 * c0; t[1] = a0b0 * c1;
                t[2] = a0b1 * c0; t[3] = a0b1 * c1;
                t[4] = a1b0 * c0; t[5] = a1b0 * c1;
                t[6] = a1b1 * c0; t[7] = a1b1 * c1;
            }
            #pragma unroll
            for (int t = 0; t < 8; t++) abp[t] = pk2(abc0[t], abc1[t]);
        }
        #pragma unroll 4
        for (int f = 0; f < NF; f++) {
            const ulonglong2* wf = (const ulonglong2*)&sm[OFF_W0D + f * 16];
            ulonglong2 Wa = wf[0], Wb = wf[1], Wc = wf[2], Wd = wf[3];
            ull v = *(const ull*)&sm[OFF_B0D + f * 2];
            v = fma2(Wa.x, abp[0], v); v = fma2(Wa.y, abp[1], v);
            v = fma2(Wb.x, abp[2], v); v = fma2(Wb.y, abp[3], v);
            v = fma2(Wc.x, abp[4], v); v = fma2(Wc.y, abp[5], v);
            v = fma2(Wd.x, abp[6], v); v = fma2(Wd.y, abp[7], v);
            float lo, hi; upk2(v, lo, hi);
            sm[OFF_Y0 + f * 516 + tid]       = fmaxf(lo, 0.0f);
            sm[OFF_Y0 + f * 516 + 256 + tid] = fmaxf(hi, 0.0f);
        }
        __syncthreads();

        // ---- conv1 (dominant GEMM, packed f32x2): lane=o, p=sub-position ----
        {
            ull acc[8] = {0,0,0,0,0,0,0,0};
            #pragma unroll 4
            for (int i = 0; i < NF; i++) {
                const float* wrow = &sm[OFF_W1P + i * 256 + lane * 2];
                ull w0 = *(const ull*)(wrow);
                ull w1 = *(const ull*)(wrow + 64);
                ull w2 = *(const ull*)(wrow + 128);
                ull w3 = *(const ull*)(wrow + 192);
                const float* xi = &sm[OFF_Y0 + i * 516];
                #pragma unroll
                for (int p = 0; p < 8; p++) {
                    const ulonglong2* xp = (const ulonglong2*)(xi + xoff[p]);
                    ulonglong2 X0 = xp[0], X1 = xp[1];    // broadcast LDS.128
                    acc[p] = fma2(w0, X0.x, acc[p]);
                    acc[p] = fma2(w1, X0.y, acc[p]);
                    acc[p] = fma2(w2, X1.x, acc[p]);
                    acc[p] = fma2(w3, X1.y, acc[p]);
                }
            }
            float b1v = sm[OFF_B1 + lane];
            float r[8];
            #pragma unroll
            for (int p = 0; p < 8; p++) {
                float lo, hi; upk2(acc[p], lo, hi);
                r[p] = fmaxf(lo + hi + b1v, 0.0f);
            }
            float4* dst = (float4*)&sm[OFF_Y1 + wq * 256 + lane * 8];
            dst[0] = make_float4(r[0], r[1], r[2], r[3]);   // STS.128 x2
            dst[1] = make_float4(r[4], r[5], r[6], r[7]);
        }
        __syncthreads();

        // ---- conv2 (packed): warp = output position wq, lane = o ----
        {
            ull a2[4] = {0,0,0,0};
            #pragma unroll 4
            for (int i = 0; i < NF; i++) {
                const ulonglong2* xq = (const ulonglong2*)&sm[OFF_Y1 + wq * 256 + i * 8];
                ulonglong2 X0 = xq[0], X1 = xq[1];        // broadcast
                const float* wrow = &sm[OFF_W2P + i * 256 + lane * 2];
                a2[0] = fma2(*(const ull*)(wrow),       X0.x, a2[0]);
                a2[1] = fma2(*(const ull*)(wrow + 64),  X0.y, a2[1]);
                a2[2] = fma2(*(const ull*)(wrow + 128), X1.x, a2[2]);
                a2[3] = fma2(*(const ull*)(wrow + 192), X1.y, a2[3]);
            }
            ull s01 = add2(a2[0], a2[1]);
            ull s23 = add2(a2[2], a2[3]);
            ull st  = add2(s01, s23);
            float lo, hi; upk2(st, lo, hi);
            float v = sm[OFF_B2 + lane] + lo + hi;
            sm[OFF_Y2 + lane * 8 + wq] = fmaxf(v, 0.0f);
        }
        __syncthreads();

        // ---- conv3 (i-split across 8 warps, scalar) + reduce + fc ----
        {
            float a3[8] = {0.f,0.f,0.f,0.f,0.f,0.f,0.f,0.f};
            #pragma unroll
            for (int ii = 0; ii < 4; ii++) {
                int i = wq * 4 + ii;
                float4 x0 = *(const float4*)&sm[OFF_Y2 + i * 8];
                float4 x1 = *(const float4*)&sm[OFF_Y2 + i * 8 + 4];
                a3[0] += sm[OFF_W3T + (i * 8 + 0) * 33 + lane] * x0.x;
                a3[1] += sm[OFF_W3T + (i * 8 + 1) * 33 + lane] * x0.y;
                a3[2] += sm[OFF_W3T + (i * 8 + 2) * 33 + lane] * x0.z;
                a3[3] += sm[OFF_W3T + (i * 8 + 3) * 33 + lane] * x0.w;
                a3[4] += sm[OFF_W3T + (i * 8 + 4) * 33 + lane] * x1.x;
                a3[5] += sm[OFF_W3T + (i * 8 + 5) * 33 + lane] * x1.y;
                a3[6] += sm[OFF_W3T + (i * 8 + 6) * 33 + lane] * x1.z;
                a3[7] += sm[OFF_W3T + (i * 8 + 7) * 33 + lane] * x1.w;
            }
            float pv = ((a3[0] + a3[1]) + (a3[2] + a3[3]))
                     + ((a3[4] + a3[5]) + (a3[6] + a3[7]));
            sm[OFF_RED + wq * 32 + lane] = pv;
        }
        __syncthreads();

        if (wq == 0) {
            float v = sm[OFF_B3 + lane];
            #pragma unroll
            for (int w = 0; w < 8; w++) v += sm[OFF_RED + w * 32 + lane];
            v = fmaxf(v, 0.0f) * sm[OFF_FCW + lane];
            #pragma unroll
            for (int off = 16; off > 0; off >>= 1)
                v += __shfl_down_sync(0xffffffffu, v, off);
            if (lane == 0)
                out[sample] = 1.0f / (1.0f + expf(-(v + fc_b)));
        }
        __syncthreads();   // protect A/B/C & RED before next iteration
    }
}

extern "C" void kernel_launch(void* const* d_in, const int* in_sizes, int n_in,
                              void* d_out, int out_size)
{
    const int*   gi  = (const int*)  d_in[0];
    const int*   gj  = (const int*)  d_in[1];
    const int*   gk  = (const int*)  d_in[2];
    const float* gA  = (const float*)d_in[3];
    const float* gB  = (const float*)d_in[4];
    const float* gC  = (const float*)d_in[5];
    const float* gW0 = (const float*)d_in[6];
    const float* gb0 = (const float*)d_in[7];
    const float* gW1 = (const float*)d_in[8];
    const float* gb1 = (const float*)d_in[9];
    const float* gW2 = (const float*)d_in[10];
    const float* gb2 = (const float*)d_in[11];
    const float* gW3 = (const float*)d_in[12];
    const float* gb3 = (const float*)d_in[13];
    const float* gfw = (const float*)d_in[14];
    const float* gfb = (const float*)d_in[15];
    float* out = (float*)d_out;

    int batch = in_sizes[0];

    int dev = 0, nsm = 148;
    cudaGetDevice(&dev);
    cudaDeviceGetAttribute(&nsm, cudaDevAttrMultiProcessorCount, dev);

    size_t smem = SMEM_FLOATS * sizeof(float);
    cudaFuncSetAttribute(ntc_fused_kernel,
                         cudaFuncAttributeMaxDynamicSharedMemorySize, (int)smem);

    ntc_fused_kernel<<<nsm, 256, smem>>>(gi, gj, gk, gA, gB, gC,
                                         gW0, gb0, gW1, gb1, gW2, gb2, gW3, gb3,
                                         gfw, gfb, out, batch, nsm);
}